// round 3
// baseline (speedup 1.0000x reference)
#include <cuda_runtime.h>
#include <math.h>

#define N_SENT      262144
#define N_BAGS      4096
#define HIDDEN      256
#define NUM_CLASSES 53
#define LCAP        2048   // logits/weights cached in smem up to this bag size

// Fallback scratch for pathological bags (> LCAP sentences). Rare/never for this seed.
__device__ float2 g_logits[N_SENT];

// ---------------------------------------------------------------------------
// Fully fused: one block per bag.
//  A: logits (warp-per-sentence dot with relation embeddings)  [x from DRAM]
//  B: softmax stats + weights in smem
//  C: weighted sum, float4 per thread, 4 sentence-groups       [x from L2]
//  D: epilogue GEMM  out[b,r] = <stack_repre, disc[r]> + bias[r]
// ---------------------------------------------------------------------------
__global__ __launch_bounds__(256) void fused_bag_kernel(
    const float4* __restrict__ x4,     // [N_SENT, 64] float4 view of x
    const float*  __restrict__ e0,     // rel_emb0 [14, 256]
    const float*  __restrict__ e1,     // rel_emb1 [53, 256]
    const float*  __restrict__ disc,   // [53, 512]
    const float*  __restrict__ bias,   // [53]
    const int*    __restrict__ rl,     // relation_levels [53, 2]
    const int*    __restrict__ li,     // label_index [N_SENT]
    const int*    __restrict__ scope,  // [N_BAGS + 1]
    float*        __restrict__ out)    // [N_BAGS, 53]
{
    __shared__ float2 s_log[LCAP];     // logits, then in-place softmax weights
    __shared__ float  s_red[16];
    __shared__ float  s_re[2 * HIDDEN];

    const int b    = blockIdx.x;
    const int tid  = threadIdx.x;
    const int lane = tid & 31;
    const int warp = tid >> 5;

    const int s0 = __ldg(scope + b);
    const int s1 = __ldg(scope + b + 1);
    const int n  = s1 - s0;
    const bool small = (n <= LCAP);

    // ---------------- phase A: per-sentence logits ----------------
    for (int j = s0 + warp; j < s1; j += 8) {
        int c  = __ldg(li + j);
        int l0 = __ldg(rl + 2 * c);
        int l1 = __ldg(rl + 2 * c + 1);

        const float4* xp = x4 + (size_t)j * 64 + lane * 2;
        float4 xa = __ldg(xp);
        float4 xb = __ldg(xp + 1);

        const float4* p0 = reinterpret_cast<const float4*>(e0 + l0 * HIDDEN) + lane * 2;
        const float4* p1 = reinterpret_cast<const float4*>(e1 + l1 * HIDDEN) + lane * 2;
        float4 ea = __ldg(p0), eb = __ldg(p0 + 1);
        float4 fa = __ldg(p1), fb = __ldg(p1 + 1);

        float g0 = xa.x * ea.x + xa.y * ea.y + xa.z * ea.z + xa.w * ea.w
                 + xb.x * eb.x + xb.y * eb.y + xb.z * eb.z + xb.w * eb.w;
        float g1 = xa.x * fa.x + xa.y * fa.y + xa.z * fa.z + xa.w * fa.w
                 + xb.x * fb.x + xb.y * fb.y + xb.z * fb.z + xb.w * fb.w;

        #pragma unroll
        for (int o = 16; o; o >>= 1) {
            g0 += __shfl_xor_sync(0xffffffffu, g0, o);
            g1 += __shfl_xor_sync(0xffffffffu, g1, o);
        }
        if (lane == 0) {
            if (small) s_log[j - s0] = make_float2(g0, g1);
            else       g_logits[j]  = make_float2(g0, g1);
        }
    }
    __syncthreads();

    // ---------------- phase B: softmax stats ----------------
    float lm0 = -INFINITY, lm1 = -INFINITY;
    for (int i = tid; i < n; i += 256) {
        float2 v = small ? s_log[i] : g_logits[s0 + i];
        lm0 = fmaxf(lm0, v.x);
        lm1 = fmaxf(lm1, v.y);
    }
    #pragma unroll
    for (int o = 16; o; o >>= 1) {
        lm0 = fmaxf(lm0, __shfl_xor_sync(0xffffffffu, lm0, o));
        lm1 = fmaxf(lm1, __shfl_xor_sync(0xffffffffu, lm1, o));
    }
    if (lane == 0) { s_red[warp] = lm0; s_red[8 + warp] = lm1; }
    __syncthreads();
    float m0 = s_red[0], m1 = s_red[8];
    #pragma unroll
    for (int k = 1; k < 8; k++) {
        m0 = fmaxf(m0, s_red[k]);
        m1 = fmaxf(m1, s_red[8 + k]);
    }
    __syncthreads();

    float ls0 = 0.f, ls1 = 0.f;
    for (int i = tid; i < n; i += 256) {
        float2 v = small ? s_log[i] : g_logits[s0 + i];
        ls0 += __expf(v.x - m0);
        ls1 += __expf(v.y - m1);
    }
    #pragma unroll
    for (int o = 16; o; o >>= 1) {
        ls0 += __shfl_xor_sync(0xffffffffu, ls0, o);
        ls1 += __shfl_xor_sync(0xffffffffu, ls1, o);
    }
    if (lane == 0) { s_red[warp] = ls0; s_red[8 + warp] = ls1; }
    __syncthreads();
    float sum0 = 0.f, sum1 = 0.f;
    #pragma unroll
    for (int k = 0; k < 8; k++) { sum0 += s_red[k]; sum1 += s_red[8 + k]; }
    const float inv0 = 1.0f / sum0;
    const float inv1 = 1.0f / sum1;

    // ---------------- phase C: weighted accumulation ----------------
    // Thread layout: sg = sentence-subgroup (0..3), d4 = float4 column (0..63).
    const int sg = tid >> 6;
    const int d4 = tid & 63;
    float4 a0 = make_float4(0.f, 0.f, 0.f, 0.f);
    float4 a1 = make_float4(0.f, 0.f, 0.f, 0.f);

    if (small) {
        __syncthreads();
        for (int i = tid; i < n; i += 256) {
            float2 v = s_log[i];
            s_log[i] = make_float2(__expf(v.x - m0) * inv0,
                                   __expf(v.y - m1) * inv1);
        }
        __syncthreads();

        #pragma unroll 2
        for (int j = sg; j < n; j += 4) {
            float2 w  = s_log[j];
            float4 xv = __ldg(x4 + (size_t)(s0 + j) * 64 + d4);
            a0.x += w.x * xv.x; a0.y += w.x * xv.y; a0.z += w.x * xv.z; a0.w += w.x * xv.w;
            a1.x += w.y * xv.x; a1.y += w.y * xv.y; a1.z += w.y * xv.z; a1.w += w.y * xv.w;
        }
    } else {
        for (int cs = 0; cs < n; cs += LCAP) {
            int cn = min(LCAP, n - cs);
            __syncthreads();
            for (int i = tid; i < cn; i += 256) {
                float2 v = g_logits[s0 + cs + i];
                s_log[i] = make_float2(__expf(v.x - m0) * inv0,
                                       __expf(v.y - m1) * inv1);
            }
            __syncthreads();
            for (int j = sg; j < cn; j += 4) {
                float2 w  = s_log[j];
                float4 xv = __ldg(x4 + (size_t)(s0 + cs + j) * 64 + d4);
                a0.x += w.x * xv.x; a0.y += w.x * xv.y; a0.z += w.x * xv.z; a0.w += w.x * xv.w;
                a1.x += w.y * xv.x; a1.y += w.y * xv.y; a1.z += w.y * xv.z; a1.w += w.y * xv.w;
            }
        }
    }

    // Combine the 4 sentence-subgroups into s_re.
    __syncthreads();
    s_re[tid]       = 0.f;
    s_re[256 + tid] = 0.f;
    __syncthreads();
    #pragma unroll
    for (int g = 0; g < 4; g++) {
        if (sg == g) {
            int base = d4 * 4;
            s_re[base + 0] += a0.x; s_re[base + 1] += a0.y;
            s_re[base + 2] += a0.z; s_re[base + 3] += a0.w;
            s_re[256 + base + 0] += a1.x; s_re[256 + base + 1] += a1.y;
            s_re[256 + base + 2] += a1.z; s_re[256 + base + 3] += a1.w;
        }
        __syncthreads();
    }

    // ---------------- phase D: epilogue GEMM ----------------
    for (int r = warp; r < NUM_CLASSES; r += 8) {
        float sum = 0.f;
        #pragma unroll
        for (int k = lane; k < 2 * HIDDEN; k += 32)
            sum += s_re[k] * __ldg(disc + r * (2 * HIDDEN) + k);
        #pragma unroll
        for (int o = 16; o; o >>= 1)
            sum += __shfl_xor_sync(0xffffffffu, sum, o);
        if (lane == 0)
            out[b * NUM_CLASSES + r] = sum + __ldg(bias + r);
    }
}

// ---------------------------------------------------------------------------
extern "C" void kernel_launch(void* const* d_in, const int* in_sizes, int n_in,
                              void* d_out, int out_size)
{
    const float* x    = (const float*)d_in[0];   // [262144, 256]
    const float* e0   = (const float*)d_in[1];   // [14, 256]
    const float* e1   = (const float*)d_in[2];   // [53, 256]
    const float* disc = (const float*)d_in[3];   // [53, 512]
    const float* bias = (const float*)d_in[4];   // [53]
    const int*   rl   = (const int*)d_in[5];     // [53, 2]
    const int*   li   = (const int*)d_in[6];     // [262144]
    const int*   sc   = (const int*)d_in[7];     // [4097]
    float* out = (float*)d_out;                  // [4096, 53]

    fused_bag_kernel<<<N_BAGS, 256>>>((const float4*)x, e0, e1, disc, bias,
                                      rl, li, sc, out);
}